// round 11
// baseline (speedup 1.0000x reference)
#include <cuda_runtime.h>
#include <math.h>

// ---------------- problem constants ----------------
#define DIMC    768
#define HEADS   12
#define HD      64
#define MLPH    3072
#define BATCH   4
#define SEQ     1024
#define MTOK    (BATCH*SEQ)      // 4096 tokens
#define QKVN    (3*DIMC)         // 2304
#define LN_EPS  1e-5f
#define ATTSCALE 0.125f          // 64^-0.5

// ---------------- packed f32x2 helpers (Blackwell FFMA2) ----------------
__device__ __forceinline__ unsigned long long pk2(float x) {
    unsigned long long r;
    asm("mov.b64 %0, {%1, %1};" : "=l"(r) : "r"(__float_as_uint(x)));
    return r;
}
__device__ __forceinline__ void fma2(unsigned long long& d,
                                     unsigned long long a,
                                     unsigned long long b) {
    asm("fma.rn.f32x2 %0, %1, %2, %0;" : "+l"(d) : "l"(a), "l"(b));
}
__device__ __forceinline__ void unpk2(unsigned long long v, float& lo, float& hi) {
    unsigned int l, h;
    asm("mov.b64 {%0, %1}, %2;" : "=r"(l), "=r"(h) : "l"(v));
    lo = __uint_as_float(l); hi = __uint_as_float(h);
}
// expand two packed accumulators into a float4 {a.lo, a.hi, b.lo, b.hi}
__device__ __forceinline__ float4 acc2f4(unsigned long long a, unsigned long long b) {
    float4 r;
    unpk2(a, r.x, r.y);
    unpk2(b, r.z, r.w);
    return r;
}

// ---------------- scratch (no allocation allowed) ----------------
__device__ float g_H  [(size_t)MTOK*DIMC];     // LN output
__device__ float g_QKV[(size_t)MTOK*QKVN];     // qkv projection
__device__ float g_AO [(size_t)MTOK*DIMC];     // merged attention output
__device__ float g_X1 [(size_t)MTOK*DIMC];     // residual stream (level 0 after attn)
__device__ float g_X2 [(size_t)MTOK*DIMC];     // residual stream (level 1)
__device__ float g_HID[(size_t)MTOK*MLPH];     // MLP hidden

// ---------------- LayerNorm: one block (192 thr) per row, float4 path ----------------
__global__ void __launch_bounds__(192) ln_kernel(const float* __restrict__ x,
                                                 const float* __restrict__ g,
                                                 const float* __restrict__ bta,
                                                 float* __restrict__ out)
{
    int row = blockIdx.x;
    const float4* xr = (const float4*)(x + (size_t)row * DIMC);
    int t = threadIdx.x;                // 0..191, DIMC/4 = 192 float4
    float4 v = xr[t];
    float s  = (v.x + v.y) + (v.z + v.w);
    float sq = (v.x*v.x + v.y*v.y) + (v.z*v.z + v.w*v.w);
#pragma unroll
    for (int o = 16; o > 0; o >>= 1) {
        s  += __shfl_xor_sync(0xffffffffu, s,  o);
        sq += __shfl_xor_sync(0xffffffffu, sq, o);
    }
    __shared__ float ws[8], wq[8];
    if ((t & 31) == 0) { ws[t>>5] = s; wq[t>>5] = sq; }
    __syncthreads();
    if (t < 32) {
        s  = (t < 6) ? ws[t] : 0.f;
        sq = (t < 6) ? wq[t] : 0.f;
#pragma unroll
        for (int o = 4; o > 0; o >>= 1) {
            s  += __shfl_xor_sync(0xffffffffu, s,  o);
            sq += __shfl_xor_sync(0xffffffffu, sq, o);
        }
        if (t == 0) { ws[0] = s; wq[0] = sq; }
    }
    __syncthreads();
    float mu  = ws[0] * (1.f/DIMC);
    float var = wq[0] * (1.f/DIMC) - mu*mu;
    float rs  = rsqrtf(var + LN_EPS);
    float4 g4 = ((const float4*)g)[t];
    float4 b4 = ((const float4*)bta)[t];
    float4 o4;
    o4.x = (v.x-mu)*rs*g4.x + b4.x;
    o4.y = (v.y-mu)*rs*g4.y + b4.y;
    o4.z = (v.z-mu)*rs*g4.z + b4.z;
    o4.w = (v.w-mu)*rs*g4.w + b4.w;
    ((float4*)(out + (size_t)row * DIMC))[t] = o4;
}

// ---------------- generic SGEMM (double-buffered, f32x2, vector epilogue) ----------------
// Tile BM x 128, K-chunk 16, 256 threads. Thread cols: {tx*4..+3} and {64+tx*4..+3}.
// MODE 0: +bias   MODE 1: +bias,GELU   MODE 2: +bias,+res
// MODE 3: 0.5*res2 + 0.5*(res + bias + gemm)
template<int MODE, int BM>
__global__ void __launch_bounds__(256, 2) sgemm_kernel(
    const float* __restrict__ A, const float* __restrict__ W,
    const float* __restrict__ bias, const float* __restrict__ res,
    const float* __restrict__ res2,
    float* __restrict__ C, int Mdim, int Ndim, int Kdim)
{
    constexpr int RI = BM / 16;               // rows per thread (8 or 4)
    constexpr int NA = BM / 64;               // A float4 fragments per thread
    constexpr int AP = BM + ((BM & 15) ? 4 : 8);  // row pad keeping 16B row alignment

    __shared__ __align__(16) float As[2][16][AP];
    __shared__ __align__(16) float Bs[2][16][128];
    int tid = threadIdx.x;
    int tx = tid & 15, ty = tid >> 4;
    int row0 = blockIdx.y * BM, col0 = blockIdx.x * 128;

    int ar[NA], ac[NA], br[2], bc[2];
#pragma unroll
    for (int i = 0; i < NA; i++) {
        int f = tid + i*256;
        ar[i] = f >> 2;  ac[i] = (f & 3) << 2;   // A tile BMx16
    }
#pragma unroll
    for (int i = 0; i < 2; i++) {
        int f = tid + i*256;
        br[i] = f >> 5;  bc[i] = (f & 31) << 2;  // W tile 16x128
    }

    unsigned long long accp[RI][4];
#pragma unroll
    for (int i = 0; i < RI; i++)
#pragma unroll
        for (int j = 0; j < 4; j++) accp[i][j] = 0ull;

    float4 a4[NA], b4[2];
#pragma unroll
    for (int i = 0; i < NA; i++)
        a4[i] = *(const float4*)(A + (size_t)(row0+ar[i])*Kdim + ac[i]);
#pragma unroll
    for (int i = 0; i < 2; i++)
        b4[i] = *(const float4*)(W + (size_t)br[i]*Ndim + col0 + bc[i]);
#pragma unroll
    for (int i = 0; i < NA; i++) {
        As[0][ac[i]+0][ar[i]] = a4[i].x; As[0][ac[i]+1][ar[i]] = a4[i].y;
        As[0][ac[i]+2][ar[i]] = a4[i].z; As[0][ac[i]+3][ar[i]] = a4[i].w;
    }
#pragma unroll
    for (int i = 0; i < 2; i++)
        *(float4*)&Bs[0][br[i]][bc[i]] = b4[i];
    __syncthreads();

    int buf = 0;
    for (int k0 = 16; k0 < Kdim; k0 += 16) {
#pragma unroll
        for (int i = 0; i < NA; i++)
            a4[i] = *(const float4*)(A + (size_t)(row0+ar[i])*Kdim + k0 + ac[i]);
#pragma unroll
        for (int i = 0; i < 2; i++)
            b4[i] = *(const float4*)(W + (size_t)(k0+br[i])*Ndim + col0 + bc[i]);
#pragma unroll
        for (int k = 0; k < 16; k++) {
            float4 av0 = *(const float4*)&As[buf][k][ty*RI];
            unsigned long long b2[4];
            b2[0] = *(const unsigned long long*)&Bs[buf][k][tx*4];
            b2[1] = *(const unsigned long long*)&Bs[buf][k][tx*4 + 2];
            b2[2] = *(const unsigned long long*)&Bs[buf][k][64 + tx*4];
            b2[3] = *(const unsigned long long*)&Bs[buf][k][64 + tx*4 + 2];
            float a_[RI];
            a_[0] = av0.x; a_[1] = av0.y; a_[2] = av0.z; a_[3] = av0.w;
            if (RI == 8) {
                float4 av1 = *(const float4*)&As[buf][k][ty*RI + 4];
                a_[4] = av1.x; a_[5] = av1.y; a_[6] = av1.z; a_[7] = av1.w;
            }
#pragma unroll
            for (int i = 0; i < RI; i++) {
                unsigned long long a2 = pk2(a_[i]);
#pragma unroll
                for (int j = 0; j < 4; j++) fma2(accp[i][j], a2, b2[j]);
            }
        }
#pragma unroll
        for (int i = 0; i < NA; i++) {
            As[buf^1][ac[i]+0][ar[i]] = a4[i].x; As[buf^1][ac[i]+1][ar[i]] = a4[i].y;
            As[buf^1][ac[i]+2][ar[i]] = a4[i].z; As[buf^1][ac[i]+3][ar[i]] = a4[i].w;
        }
#pragma unroll
        for (int i = 0; i < 2; i++)
            *(float4*)&Bs[buf^1][br[i]][bc[i]] = b4[i];
        __syncthreads();
        buf ^= 1;
    }
#pragma unroll
    for (int k = 0; k < 16; k++) {
        float4 av0 = *(const float4*)&As[buf][k][ty*RI];
        unsigned long long b2[4];
        b2[0] = *(const unsigned long long*)&Bs[buf][k][tx*4];
        b2[1] = *(const unsigned long long*)&Bs[buf][k][tx*4 + 2];
        b2[2] = *(const unsigned long long*)&Bs[buf][k][64 + tx*4];
        b2[3] = *(const unsigned long long*)&Bs[buf][k][64 + tx*4 + 2];
        float a_[RI];
        a_[0] = av0.x; a_[1] = av0.y; a_[2] = av0.z; a_[3] = av0.w;
        if (RI == 8) {
            float4 av1 = *(const float4*)&As[buf][k][ty*RI + 4];
            a_[4] = av1.x; a_[5] = av1.y; a_[6] = av1.z; a_[7] = av1.w;
        }
#pragma unroll
        for (int i = 0; i < RI; i++) {
            unsigned long long a2 = pk2(a_[i]);
#pragma unroll
            for (int j = 0; j < 4; j++) fma2(accp[i][j], a2, b2[j]);
        }
    }

    // ---- vector epilogue: two float4 groups per row ----
    float4 bias0 = *(const float4*)&bias[col0 + tx*4];
    float4 bias1 = *(const float4*)&bias[col0 + 64 + tx*4];
#pragma unroll
    for (int i = 0; i < RI; i++) {
        int r = row0 + ty*RI + i;
        float4 v0 = acc2f4(accp[i][0], accp[i][1]);
        float4 v1 = acc2f4(accp[i][2], accp[i][3]);
        v0.x += bias0.x; v0.y += bias0.y; v0.z += bias0.z; v0.w += bias0.w;
        v1.x += bias1.x; v1.y += bias1.y; v1.z += bias1.z; v1.w += bias1.w;
        if (MODE == 1) {
            v0.x = 0.5f*v0.x*(1.0f+erff(v0.x*0.70710678118654752f));
            v0.y = 0.5f*v0.y*(1.0f+erff(v0.y*0.70710678118654752f));
            v0.z = 0.5f*v0.z*(1.0f+erff(v0.z*0.70710678118654752f));
            v0.w = 0.5f*v0.w*(1.0f+erff(v0.w*0.70710678118654752f));
            v1.x = 0.5f*v1.x*(1.0f+erff(v1.x*0.70710678118654752f));
            v1.y = 0.5f*v1.y*(1.0f+erff(v1.y*0.70710678118654752f));
            v1.z = 0.5f*v1.z*(1.0f+erff(v1.z*0.70710678118654752f));
            v1.w = 0.5f*v1.w*(1.0f+erff(v1.w*0.70710678118654752f));
        }
        if (MODE == 2) {
            float4 r0 = *(const float4*)&res[(size_t)r*Ndim + col0 + tx*4];
            float4 r1 = *(const float4*)&res[(size_t)r*Ndim + col0 + 64 + tx*4];
            v0.x += r0.x; v0.y += r0.y; v0.z += r0.z; v0.w += r0.w;
            v1.x += r1.x; v1.y += r1.y; v1.z += r1.z; v1.w += r1.w;
        }
        if (MODE == 3) {
            float4 r0 = *(const float4*)&res[(size_t)r*Ndim + col0 + tx*4];
            float4 r1 = *(const float4*)&res[(size_t)r*Ndim + col0 + 64 + tx*4];
            float4 s0 = *(const float4*)&res2[(size_t)r*Ndim + col0 + tx*4];
            float4 s1 = *(const float4*)&res2[(size_t)r*Ndim + col0 + 64 + tx*4];
            v0.x = 0.5f*s0.x + 0.5f*(r0.x + v0.x);
            v0.y = 0.5f*s0.y + 0.5f*(r0.y + v0.y);
            v0.z = 0.5f*s0.z + 0.5f*(r0.z + v0.z);
            v0.w = 0.5f*s0.w + 0.5f*(r0.w + v0.w);
            v1.x = 0.5f*s1.x + 0.5f*(r1.x + v1.x);
            v1.y = 0.5f*s1.y + 0.5f*(r1.y + v1.y);
            v1.z = 0.5f*s1.z + 0.5f*(r1.z + v1.z);
            v1.w = 0.5f*s1.w + 0.5f*(r1.w + v1.w);
        }
        *(float4*)&C[(size_t)r*Ndim + col0 + tx*4]      = v0;
        *(float4*)&C[(size_t)r*Ndim + col0 + 64 + tx*4] = v1;
    }
}

// ---------------- attention scores (double-buffered, f32x2, vector stores) ----------------
__global__ void __launch_bounds__(256, 2) attn_scores_kernel(
    const float* __restrict__ qkv, float* __restrict__ attn)
{
    int bh = blockIdx.z;
    int bb = bh / HEADS, h = bh % HEADS;
    const float* Q = qkv + (size_t)bb*SEQ*QKVN + h*HD;
    const float* Kp = Q + DIMC;
    float* Cp = attn + (size_t)bh*SEQ*SEQ;
    int n0 = blockIdx.y * 128, m0 = blockIdx.x * 128;

    __shared__ __align__(16) float Qs[2][16][132];
    __shared__ __align__(16) float Ks[2][16][132];
    int tid = threadIdx.x;
    int tx = tid & 15, ty = tid >> 4;

    int lr[2], lc[2];
#pragma unroll
    for (int i = 0; i < 2; i++) {
        int f = tid + i*256;
        lr[i] = f >> 2; lc[i] = (f & 3) << 2;
    }

    unsigned long long accp[8][4];
#pragma unroll
    for (int i = 0; i < 8; i++)
#pragma unroll
        for (int j = 0; j < 4; j++) accp[i][j] = 0ull;

    float4 q4[2], k4[2];
#pragma unroll
    for (int i = 0; i < 2; i++) {
        q4[i] = *(const float4*)(Q  + (size_t)(n0+lr[i])*QKVN + lc[i]);
        k4[i] = *(const float4*)(Kp + (size_t)(m0+lr[i])*QKVN + lc[i]);
    }
#pragma unroll
    for (int i = 0; i < 2; i++) {
        Qs[0][lc[i]+0][lr[i]] = q4[i].x; Qs[0][lc[i]+1][lr[i]] = q4[i].y;
        Qs[0][lc[i]+2][lr[i]] = q4[i].z; Qs[0][lc[i]+3][lr[i]] = q4[i].w;
        Ks[0][lc[i]+0][lr[i]] = k4[i].x; Ks[0][lc[i]+1][lr[i]] = k4[i].y;
        Ks[0][lc[i]+2][lr[i]] = k4[i].z; Ks[0][lc[i]+3][lr[i]] = k4[i].w;
    }
    __syncthreads();

    int buf = 0;
    for (int d0 = 16; d0 < HD; d0 += 16) {
#pragma unroll
        for (int i = 0; i < 2; i++) {
            q4[i] = *(const float4*)(Q  + (size_t)(n0+lr[i])*QKVN + d0 + lc[i]);
            k4[i] = *(const float4*)(Kp + (size_t)(m0+lr[i])*QKVN + d0 + lc[i]);
        }
#pragma unroll
        for (int k = 0; k < 16; k++) {
            float4 av0 = *(const float4*)&Qs[buf][k][ty*8];
            float4 av1 = *(const float4*)&Qs[buf][k][ty*8 + 4];
            unsigned long long b2[4];
            b2[0] = *(const unsigned long long*)&Ks[buf][k][tx*4];
            b2[1] = *(const unsigned long long*)&Ks[buf][k][tx*4 + 2];
            b2[2] = *(const unsigned long long*)&Ks[buf][k][64 + tx*4];
            b2[3] = *(const unsigned long long*)&Ks[buf][k][64 + tx*4 + 2];
            float a_[8] = {av0.x, av0.y, av0.z, av0.w, av1.x, av1.y, av1.z, av1.w};
#pragma unroll
            for (int i = 0; i < 8; i++) {
                unsigned long long a2 = pk2(a_[i]);
#pragma unroll
                for (int j = 0; j < 4; j++) fma2(accp[i][j], a2, b2[j]);
            }
        }
#pragma unroll
        for (int i = 0; i < 2; i++) {
            Qs[buf^1][lc[i]+0][lr[i]] = q4[i].x; Qs[buf^1][lc[i]+1][lr[i]] = q4[i].y;
            Qs[buf^1][lc[i]+2][lr[i]] = q4[i].z; Qs[buf^1][lc[i]+3][lr[i]] = q4[i].w;
            Ks[buf^1][lc[i]+0][lr[i]] = k4[i].x; Ks[buf^1][lc[i]+1][lr[i]] = k4[i].y;
            Ks[buf^1][lc[i]+2][lr[i]] = k4[i].z; Ks[buf^1][lc[i]+3][lr[i]] = k4[i].w;
        }
        __syncthreads();
        buf ^= 1;
    }
#pragma unroll
    for (int k = 0; k < 16; k++) {
        float4 av0 = *(const float4*)&Qs[buf][k][ty*8];
        float4 av1 = *(const float4*)&Qs[buf][k][ty*8 + 4];
        unsigned long long b2[4];
        b2[0] = *(const unsigned long long*)&Ks[buf][k][tx*4];
        b2[1] = *(const unsigned long long*)&Ks[buf][k][tx*4 + 2];
        b2[2] = *(const unsigned long long*)&Ks[buf][k][64 + tx*4];
        b2[3] = *(const unsigned long long*)&Ks[buf][k][64 + tx*4 + 2];
        float a_[8] = {av0.x, av0.y, av0.z, av0.w, av1.x, av1.y, av1.z, av1.w};
#pragma unroll
        for (int i = 0; i < 8; i++) {
            unsigned long long a2 = pk2(a_[i]);
#pragma unroll
            for (int j = 0; j < 4; j++) fma2(accp[i][j], a2, b2[j]);
        }
    }

#pragma unroll
    for (int i = 0; i < 8; i++) {
        size_t r = n0 + ty*8 + i;
        float4 v0 = acc2f4(accp[i][0], accp[i][1]);
        float4 v1 = acc2f4(accp[i][2], accp[i][3]);
        v0.x *= ATTSCALE; v0.y *= ATTSCALE; v0.z *= ATTSCALE; v0.w *= ATTSCALE;
        v1.x *= ATTSCALE; v1.y *= ATTSCALE; v1.z *= ATTSCALE; v1.w *= ATTSCALE;
        *(float4*)&Cp[r*SEQ + m0 + tx*4]      = v0;
        *(float4*)&Cp[r*SEQ + m0 + 64 + tx*4] = v1;
    }
}

// ---------------- softmax per row of 1024 (in place, float4, fast exp) ----------------
__global__ void __launch_bounds__(256) softmax_kernel(float* __restrict__ attn)
{
    float4* p = (float4*)(attn + (size_t)blockIdx.x * SEQ);
    int t = threadIdx.x;
    float4 v = p[t];
    float mx = fmaxf(fmaxf(v.x, v.y), fmaxf(v.z, v.w));
#pragma unroll
    for (int o = 16; o > 0; o >>= 1) mx = fmaxf(mx, __shfl_xor_sync(0xffffffffu, mx, o));
    __shared__ float wm[8], wsum[8];
    if ((t & 31) == 0) wm[t>>5] = mx;
    __syncthreads();
    if (t < 32) {
        mx = (t < 8) ? wm[t] : -3.0e38f;
#pragma unroll
        for (int o = 4; o > 0; o >>= 1) mx = fmaxf(mx, __shfl_xor_sync(0xffffffffu, mx, o));
        if (t == 0) wm[0] = mx;
    }
    __syncthreads();
    mx = wm[0];
    v.x = __expf(v.x - mx); v.y = __expf(v.y - mx);
    v.z = __expf(v.z - mx); v.w = __expf(v.w - mx);
    float s = (v.x + v.y) + (v.z + v.w);
#pragma unroll
    for (int o = 16; o > 0; o >>= 1) s += __shfl_xor_sync(0xffffffffu, s, o);
    if ((t & 31) == 0) wsum[t>>5] = s;
    __syncthreads();
    if (t < 32) {
        s = (t < 8) ? wsum[t] : 0.f;
#pragma unroll
        for (int o = 4; o > 0; o >>= 1) s += __shfl_xor_sync(0xffffffffu, s, o);
        if (t == 0) wsum[0] = s;
    }
    __syncthreads();
    float inv = 1.f / wsum[0];
    v.x *= inv; v.y *= inv; v.z *= inv; v.w *= inv;
    p[t] = v;
}

// ---------------- attn @ V (double-buffered, f32x2, vector stores) ----------------
__global__ void __launch_bounds__(256) attn_av_kernel(
    const float* __restrict__ attn, const float* __restrict__ qkv,
    float* __restrict__ AO)
{
    int bh = blockIdx.y;
    int bb = bh / HEADS, h = bh % HEADS;
    const float* Ap = attn + (size_t)bh*SEQ*SEQ;
    const float* V  = qkv + (size_t)bb*SEQ*QKVN + 2*DIMC + h*HD;
    int n0 = blockIdx.x * 128;

    __shared__ __align__(16) float As[2][32][132];
    __shared__ __align__(16) float Vs[2][32][72];
    int tid = threadIdx.x;
    int tx = tid & 15, ty = tid >> 4;

    int arr[4], colc[4], vr[2], vc[2];
#pragma unroll
    for (int i = 0; i < 4; i++) {
        int f = tid + i*256;
        arr[i] = f >> 3; colc[i] = (f & 7) << 2;
    }
#pragma unroll
    for (int i = 0; i < 2; i++) {
        int f = tid + i*256;
        vr[i] = f >> 4; vc[i] = (f & 15) << 2;
    }

    unsigned long long accp[8][2];
#pragma unroll
    for (int i = 0; i < 8; i++)
#pragma unroll
        for (int j = 0; j < 2; j++) accp[i][j] = 0ull;

    float4 a4[4], v4[2];
#pragma unroll
    for (int i = 0; i < 4; i++)
        a4[i] = *(const float4*)(Ap + (size_t)(n0+arr[i])*SEQ + colc[i]);
#pragma unroll
    for (int i = 0; i < 2; i++)
        v4[i] = *(const float4*)(V + (size_t)vr[i]*QKVN + vc[i]);
#pragma unroll
    for (int i = 0; i < 4; i++) {
        As[0][colc[i]+0][arr[i]] = a4[i].x; As[0][colc[i]+1][arr[i]] = a4[i].y;
        As[0][colc[i]+2][arr[i]] = a4[i].z; As[0][colc[i]+3][arr[i]] = a4[i].w;
    }
#pragma unroll
    for (int i = 0; i < 2; i++)
        *(float4*)&Vs[0][vr[i]][vc[i]] = v4[i];
    __syncthreads();

    int buf = 0;
    for (int m0 = 32; m0 < SEQ; m0 += 32) {
#pragma unroll
        for (int i = 0; i < 4; i++)
            a4[i] = *(const float4*)(Ap + (size_t)(n0+arr[i])*SEQ + m0 + colc[i]);
#pragma unroll
        for (int i = 0; i < 2; i++)
            v4[i] = *(const float4*)(V + (size_t)(m0+vr[i])*QKVN + vc[i]);
#pragma unroll
        for (int k = 0; k < 32; k++) {
            float4 av0 = *(const float4*)&As[buf][k][ty*8];
            float4 av1 = *(const float4*)&As[buf][k][ty*8 + 4];
            unsigned long long b2[2];
            b2[0] = *(const unsigned long long*)&Vs[buf][k][tx*4];
            b2[1] = *(const unsigned long long*)&Vs[buf][k][tx*4 + 2];
            float a_[8] = {av0.x, av0.y, av0.z, av0.w, av1.x, av1.y, av1.z, av1.w};
#pragma unroll
            for (int i = 0; i < 8; i++) {
                unsigned long long a2 = pk2(a_[i]);
#pragma unroll
                for (int j = 0; j < 2; j++) fma2(accp[i][j], a2, b2[j]);
            }
        }
#pragma unroll
        for (int i = 0; i < 4; i++) {
            As[buf^1][colc[i]+0][arr[i]] = a4[i].x; As[buf^1][colc[i]+1][arr[i]] = a4[i].y;
            As[buf^1][colc[i]+2][arr[i]] = a4[i].z; As[buf^1][colc[i]+3][arr[i]] = a4[i].w;
        }
#pragma unroll
        for (int i = 0; i < 2; i++)
            *(float4*)&Vs[buf^1][vr[i]][vc[i]] = v4[i];
        __syncthreads();
        buf ^= 1;
    }
#pragma unroll
    for (int k = 0; k < 32; k++) {
        float4 av0 = *(const float4*)&As[buf][k][ty*8];
        float4 av1 = *(const float4*)&As[buf][k][ty*8 + 4];
        unsigned long long b2[2];
        b2[0] = *(const unsigned long long*)&Vs[buf][k][tx*4];
        b2[1] = *(const unsigned long long*)&Vs[buf][k][tx*4 + 2];
        float a_[8] = {av0.x, av0.y, av0.z, av0.w, av1.x, av1.y, av1.z, av1.w};
#pragma unroll
        for (int i = 0; i < 8; i++) {
            unsigned long long a2 = pk2(a_[i]);
#pragma unroll
            for (int j = 0; j < 2; j++) fma2(accp[i][j], a2, b2[j]);
        }
    }

#pragma unroll
    for (int i = 0; i < 8; i++) {
        size_t n = (size_t)bb*SEQ + n0 + ty*8 + i;
        float4 v0 = acc2f4(accp[i][0], accp[i][1]);
        *(float4*)&AO[n*DIMC + h*HD + tx*4] = v0;
    }
}

// ---------------- driver ----------------
extern "C" void kernel_launch(void* const* d_in, const int* in_sizes, int n_in,
                              void* d_out, int out_size)
{
    const float* x = (const float*)d_in[0];
    const float* P[25];
    for (int i = 0; i < 25; i++) P[i] = (const float*)d_in[i];

    float* out   = (float*)d_out;
    float* attn0 = out + (size_t)MTOK * DIMC;
    float* attn1 = attn0 + (size_t)BATCH*HEADS*SEQ*SEQ;

    float *H, *QKV, *AO, *X1, *X2, *HID;
    cudaGetSymbolAddress((void**)&H,   g_H);
    cudaGetSymbolAddress((void**)&QKV, g_QKV);
    cudaGetSymbolAddress((void**)&AO,  g_AO);
    cudaGetSymbolAddress((void**)&X1,  g_X1);
    cudaGetSymbolAddress((void**)&X2,  g_X2);
    cudaGetSymbolAddress((void**)&HID, g_HID);

    dim3 gQKV(QKVN/128, MTOK/128);     // (18, 32)  BM=128
    dim3 gPROJ(DIMC/128, MTOK/64);     // (6, 64)   BM=64 — better wave balance
    dim3 gMLP1(MLPH/128, MTOK/128);    // (24, 32)  BM=128
    dim3 gSC(SEQ/128, SEQ/128, BATCH*HEADS);  // (8, 8, 48)
    dim3 gAV(SEQ/128, BATCH*HEADS);           // (8, 48)
    int  gSM = BATCH*HEADS*SEQ;               // 49152 softmax rows

    // ===== level 0: attention =====
    ln_kernel<<<MTOK, 192>>>(x, P[5], P[6], H);
    sgemm_kernel<0,128><<<gQKV, 256>>>(H, P[1], P[2], nullptr, nullptr, QKV, MTOK, QKVN, DIMC);
    attn_scores_kernel<<<gSC, 256>>>(QKV, attn0);
    softmax_kernel<<<gSM, 256>>>(attn0);
    attn_av_kernel<<<gAV, 256>>>(attn0, QKV, AO);
    sgemm_kernel<2,64><<<gPROJ, 256>>>(AO, P[3], P[4], x, nullptr, X1, MTOK, DIMC, DIMC);

    // ===== level 1 (inner block on X1) =====
    ln_kernel<<<MTOK, 192>>>(X1, P[17], P[18], H);
    sgemm_kernel<0,128><<<gQKV, 256>>>(H, P[13], P[14], nullptr, nullptr, QKV, MTOK, QKVN, DIMC);
    attn_scores_kernel<<<gSC, 256>>>(QKV, attn1);
    softmax_kernel<<<gSM, 256>>>(attn1);
    attn_av_kernel<<<gAV, 256>>>(attn1, QKV, AO);
    sgemm_kernel<2,64><<<gPROJ, 256>>>(AO, P[15], P[16], X1, nullptr, X2, MTOK, DIMC, DIMC);
    // inner MLP (MLP2 epilogue fuses the level-0 blend: X1 = 0.5*X1 + 0.5*(X2 + mlp_out))
    ln_kernel<<<MTOK, 192>>>(X2, P[19], P[20], H);
    sgemm_kernel<1,128><<<gMLP1, 256>>>(H, P[21], P[22], nullptr, nullptr, HID, MTOK, MLPH, DIMC);
    sgemm_kernel<3,64><<<gPROJ, 256>>>(HID, P[23], P[24], X2, X1, X1, MTOK, DIMC, MLPH);

    // ===== level 0: MLP =====
    ln_kernel<<<MTOK, 192>>>(X1, P[7], P[8], H);
    sgemm_kernel<1,128><<<gMLP1, 256>>>(H, P[9], P[10], nullptr, nullptr, HID, MTOK, MLPH, DIMC);
    sgemm_kernel<2,64><<<gPROJ, 256>>>(HID, P[11], P[12], X1, nullptr, out, MTOK, DIMC, MLPH);
}

// round 12
// speedup vs baseline: 1.0616x; 1.0616x over previous
#include <cuda_runtime.h>
#include <math.h>

// ---------------- problem constants ----------------
#define DIMC    768
#define HEADS   12
#define HD      64
#define MLPH    3072
#define BATCH   4
#define SEQ     1024
#define MTOK    (BATCH*SEQ)      // 4096 tokens
#define QKVN    (3*DIMC)         // 2304
#define LN_EPS  1e-5f
#define ATTSCALE 0.125f          // 64^-0.5

// ---------------- packed f32x2 helpers (Blackwell FFMA2) ----------------
__device__ __forceinline__ unsigned long long pk2(float x) {
    unsigned long long r;
    asm("mov.b64 %0, {%1, %1};" : "=l"(r) : "r"(__float_as_uint(x)));
    return r;
}
__device__ __forceinline__ void fma2(unsigned long long& d,
                                     unsigned long long a,
                                     unsigned long long b) {
    asm("fma.rn.f32x2 %0, %1, %2, %0;" : "+l"(d) : "l"(a), "l"(b));
}
__device__ __forceinline__ void unpk2(unsigned long long v, float& lo, float& hi) {
    unsigned int l, h;
    asm("mov.b64 {%0, %1}, %2;" : "=r"(l), "=r"(h) : "l"(v));
    lo = __uint_as_float(l); hi = __uint_as_float(h);
}
// expand two packed accumulators into a float4 {a.lo, a.hi, b.lo, b.hi}
__device__ __forceinline__ float4 acc2f4(unsigned long long a, unsigned long long b) {
    float4 r;
    unpk2(a, r.x, r.y);
    unpk2(b, r.z, r.w);
    return r;
}

// ---------------- scratch (no allocation allowed) ----------------
__device__ float g_H  [(size_t)MTOK*DIMC];     // LN output
__device__ float g_QKV[(size_t)MTOK*QKVN];     // qkv projection
__device__ float g_AO [(size_t)MTOK*DIMC];     // merged attention output
__device__ float g_X1 [(size_t)MTOK*DIMC];     // residual stream (level 0 after attn)
__device__ float g_X2 [(size_t)MTOK*DIMC];     // residual stream (level 1)
__device__ float g_HID[(size_t)MTOK*MLPH];     // MLP hidden

// ---------------- LayerNorm: one WARP per row (shuffle-only, no barriers) ----------------
// 256 threads = 8 warps = 8 rows per block. Each lane: 6 float4 (768 = 32*6*4).
__global__ void __launch_bounds__(256) ln_kernel(const float* __restrict__ x,
                                                 const float* __restrict__ g,
                                                 const float* __restrict__ bta,
                                                 float* __restrict__ out)
{
    int w = threadIdx.x >> 5, lane = threadIdx.x & 31;
    size_t row = (size_t)blockIdx.x * 8 + w;
    const float4* xr = (const float4*)(x + row * DIMC);
    float4 v[6];
    float s = 0.f, sq = 0.f;
#pragma unroll
    for (int i = 0; i < 6; i++) {
        v[i] = xr[lane + 32*i];
        s  += (v[i].x + v[i].y) + (v[i].z + v[i].w);
        sq += (v[i].x*v[i].x + v[i].y*v[i].y) + (v[i].z*v[i].z + v[i].w*v[i].w);
    }
#pragma unroll
    for (int o = 16; o > 0; o >>= 1) {
        s  += __shfl_xor_sync(0xffffffffu, s,  o);
        sq += __shfl_xor_sync(0xffffffffu, sq, o);
    }
    float mu  = s * (1.f/DIMC);
    float var = sq * (1.f/DIMC) - mu*mu;
    float rs  = rsqrtf(var + LN_EPS);
    float4* orow = (float4*)(out + row * DIMC);
#pragma unroll
    for (int i = 0; i < 6; i++) {
        float4 g4 = ((const float4*)g)[lane + 32*i];
        float4 b4 = ((const float4*)bta)[lane + 32*i];
        float4 o4;
        o4.x = (v[i].x-mu)*rs*g4.x + b4.x;
        o4.y = (v[i].y-mu)*rs*g4.y + b4.y;
        o4.z = (v[i].z-mu)*rs*g4.z + b4.z;
        o4.w = (v[i].w-mu)*rs*g4.w + b4.w;
        orow[lane + 32*i] = o4;
    }
}

// ---------------- generic SGEMM (double-buffered, f32x2, vector epilogue) ----------------
// Tile BM x 128, K-chunk 16, 256 threads. Thread cols: {tx*4..+3} and {64+tx*4..+3}.
// MODE 0: +bias   MODE 1: +bias,GELU   MODE 2: +bias,+res
// MODE 3: 0.5*res2 + 0.5*(res + bias + gemm)
template<int MODE, int BM>
__global__ void __launch_bounds__(256, 2) sgemm_kernel(
    const float* __restrict__ A, const float* __restrict__ W,
    const float* __restrict__ bias, const float* __restrict__ res,
    const float* __restrict__ res2,
    float* __restrict__ C, int Mdim, int Ndim, int Kdim)
{
    constexpr int RI = BM / 16;               // rows per thread (8 or 4)
    constexpr int NA = BM / 64;               // A float4 fragments per thread
    constexpr int AP = BM + ((BM & 15) ? 4 : 8);  // row pad keeping 16B row alignment

    __shared__ __align__(16) float As[2][16][AP];
    __shared__ __align__(16) float Bs[2][16][128];
    int tid = threadIdx.x;
    int tx = tid & 15, ty = tid >> 4;
    int row0 = blockIdx.y * BM, col0 = blockIdx.x * 128;

    int ar[NA], ac[NA], br[2], bc[2];
#pragma unroll
    for (int i = 0; i < NA; i++) {
        int f = tid + i*256;
        ar[i] = f >> 2;  ac[i] = (f & 3) << 2;   // A tile BMx16
    }
#pragma unroll
    for (int i = 0; i < 2; i++) {
        int f = tid + i*256;
        br[i] = f >> 5;  bc[i] = (f & 31) << 2;  // W tile 16x128
    }

    unsigned long long accp[RI][4];
#pragma unroll
    for (int i = 0; i < RI; i++)
#pragma unroll
        for (int j = 0; j < 4; j++) accp[i][j] = 0ull;

    float4 a4[NA], b4[2];
#pragma unroll
    for (int i = 0; i < NA; i++)
        a4[i] = *(const float4*)(A + (size_t)(row0+ar[i])*Kdim + ac[i]);
#pragma unroll
    for (int i = 0; i < 2; i++)
        b4[i] = *(const float4*)(W + (size_t)br[i]*Ndim + col0 + bc[i]);
#pragma unroll
    for (int i = 0; i < NA; i++) {
        As[0][ac[i]+0][ar[i]] = a4[i].x; As[0][ac[i]+1][ar[i]] = a4[i].y;
        As[0][ac[i]+2][ar[i]] = a4[i].z; As[0][ac[i]+3][ar[i]] = a4[i].w;
    }
#pragma unroll
    for (int i = 0; i < 2; i++)
        *(float4*)&Bs[0][br[i]][bc[i]] = b4[i];
    __syncthreads();

    int buf = 0;
    for (int k0 = 16; k0 < Kdim; k0 += 16) {
#pragma unroll
        for (int i = 0; i < NA; i++)
            a4[i] = *(const float4*)(A + (size_t)(row0+ar[i])*Kdim + k0 + ac[i]);
#pragma unroll
        for (int i = 0; i < 2; i++)
            b4[i] = *(const float4*)(W + (size_t)(k0+br[i])*Ndim + col0 + bc[i]);
#pragma unroll
        for (int k = 0; k < 16; k++) {
            float4 av0 = *(const float4*)&As[buf][k][ty*RI];
            unsigned long long b2[4];
            b2[0] = *(const unsigned long long*)&Bs[buf][k][tx*4];
            b2[1] = *(const unsigned long long*)&Bs[buf][k][tx*4 + 2];
            b2[2] = *(const unsigned long long*)&Bs[buf][k][64 + tx*4];
            b2[3] = *(const unsigned long long*)&Bs[buf][k][64 + tx*4 + 2];
            float a_[RI];
            a_[0] = av0.x; a_[1] = av0.y; a_[2] = av0.z; a_[3] = av0.w;
            if (RI == 8) {
                float4 av1 = *(const float4*)&As[buf][k][ty*RI + 4];
                a_[4] = av1.x; a_[5] = av1.y; a_[6] = av1.z; a_[7] = av1.w;
            }
#pragma unroll
            for (int i = 0; i < RI; i++) {
                unsigned long long a2 = pk2(a_[i]);
#pragma unroll
                for (int j = 0; j < 4; j++) fma2(accp[i][j], a2, b2[j]);
            }
        }
#pragma unroll
        for (int i = 0; i < NA; i++) {
            As[buf^1][ac[i]+0][ar[i]] = a4[i].x; As[buf^1][ac[i]+1][ar[i]] = a4[i].y;
            As[buf^1][ac[i]+2][ar[i]] = a4[i].z; As[buf^1][ac[i]+3][ar[i]] = a4[i].w;
        }
#pragma unroll
        for (int i = 0; i < 2; i++)
            *(float4*)&Bs[buf^1][br[i]][bc[i]] = b4[i];
        __syncthreads();
        buf ^= 1;
    }
#pragma unroll
    for (int k = 0; k < 16; k++) {
        float4 av0 = *(const float4*)&As[buf][k][ty*RI];
        unsigned long long b2[4];
        b2[0] = *(const unsigned long long*)&Bs[buf][k][tx*4];
        b2[1] = *(const unsigned long long*)&Bs[buf][k][tx*4 + 2];
        b2[2] = *(const unsigned long long*)&Bs[buf][k][64 + tx*4];
        b2[3] = *(const unsigned long long*)&Bs[buf][k][64 + tx*4 + 2];
        float a_[RI];
        a_[0] = av0.x; a_[1] = av0.y; a_[2] = av0.z; a_[3] = av0.w;
        if (RI == 8) {
            float4 av1 = *(const float4*)&As[buf][k][ty*RI + 4];
            a_[4] = av1.x; a_[5] = av1.y; a_[6] = av1.z; a_[7] = av1.w;
        }
#pragma unroll
        for (int i = 0; i < RI; i++) {
            unsigned long long a2 = pk2(a_[i]);
#pragma unroll
            for (int j = 0; j < 4; j++) fma2(accp[i][j], a2, b2[j]);
        }
    }

    // ---- vector epilogue: two float4 groups per row ----
    float4 bias0 = *(const float4*)&bias[col0 + tx*4];
    float4 bias1 = *(const float4*)&bias[col0 + 64 + tx*4];
#pragma unroll
    for (int i = 0; i < RI; i++) {
        int r = row0 + ty*RI + i;
        float4 v0 = acc2f4(accp[i][0], accp[i][1]);
        float4 v1 = acc2f4(accp[i][2], accp[i][3]);
        v0.x += bias0.x; v0.y += bias0.y; v0.z += bias0.z; v0.w += bias0.w;
        v1.x += bias1.x; v1.y += bias1.y; v1.z += bias1.z; v1.w += bias1.w;
        if (MODE == 1) {
            v0.x = 0.5f*v0.x*(1.0f+erff(v0.x*0.70710678118654752f));
            v0.y = 0.5f*v0.y*(1.0f+erff(v0.y*0.70710678118654752f));
            v0.z = 0.5f*v0.z*(1.0f+erff(v0.z*0.70710678118654752f));
            v0.w = 0.5f*v0.w*(1.0f+erff(v0.w*0.70710678118654752f));
            v1.x = 0.5f*v1.x*(1.0f+erff(v1.x*0.70710678118654752f));
            v1.y = 0.5f*v1.y*(1.0f+erff(v1.y*0.70710678118654752f));
            v1.z = 0.5f*v1.z*(1.0f+erff(v1.z*0.70710678118654752f));
            v1.w = 0.5f*v1.w*(1.0f+erff(v1.w*0.70710678118654752f));
        }
        if (MODE == 2) {
            float4 r0 = *(const float4*)&res[(size_t)r*Ndim + col0 + tx*4];
            float4 r1 = *(const float4*)&res[(size_t)r*Ndim + col0 + 64 + tx*4];
            v0.x += r0.x; v0.y += r0.y; v0.z += r0.z; v0.w += r0.w;
            v1.x += r1.x; v1.y += r1.y; v1.z += r1.z; v1.w += r1.w;
        }
        if (MODE == 3) {
            float4 r0 = *(const float4*)&res[(size_t)r*Ndim + col0 + tx*4];
            float4 r1 = *(const float4*)&res[(size_t)r*Ndim + col0 + 64 + tx*4];
            float4 s0 = *(const float4*)&res2[(size_t)r*Ndim + col0 + tx*4];
            float4 s1 = *(const float4*)&res2[(size_t)r*Ndim + col0 + 64 + tx*4];
            v0.x = 0.5f*s0.x + 0.5f*(r0.x + v0.x);
            v0.y = 0.5f*s0.y + 0.5f*(r0.y + v0.y);
            v0.z = 0.5f*s0.z + 0.5f*(r0.z + v0.z);
            v0.w = 0.5f*s0.w + 0.5f*(r0.w + v0.w);
            v1.x = 0.5f*s1.x + 0.5f*(r1.x + v1.x);
            v1.y = 0.5f*s1.y + 0.5f*(r1.y + v1.y);
            v1.z = 0.5f*s1.z + 0.5f*(r1.z + v1.z);
            v1.w = 0.5f*s1.w + 0.5f*(r1.w + v1.w);
        }
        *(float4*)&C[(size_t)r*Ndim + col0 + tx*4]      = v0;
        *(float4*)&C[(size_t)r*Ndim + col0 + 64 + tx*4] = v1;
    }
}

// ---------------- attention scores (double-buffered, f32x2, vector stores) ----------------
__global__ void __launch_bounds__(256, 2) attn_scores_kernel(
    const float* __restrict__ qkv, float* __restrict__ attn)
{
    int bh = blockIdx.z;
    int bb = bh / HEADS, h = bh % HEADS;
    const float* Q = qkv + (size_t)bb*SEQ*QKVN + h*HD;
    const float* Kp = Q + DIMC;
    float* Cp = attn + (size_t)bh*SEQ*SEQ;
    int n0 = blockIdx.y * 128, m0 = blockIdx.x * 128;

    __shared__ __align__(16) float Qs[2][16][132];
    __shared__ __align__(16) float Ks[2][16][132];
    int tid = threadIdx.x;
    int tx = tid & 15, ty = tid >> 4;

    int lr[2], lc[2];
#pragma unroll
    for (int i = 0; i < 2; i++) {
        int f = tid + i*256;
        lr[i] = f >> 2; lc[i] = (f & 3) << 2;
    }

    unsigned long long accp[8][4];
#pragma unroll
    for (int i = 0; i < 8; i++)
#pragma unroll
        for (int j = 0; j < 4; j++) accp[i][j] = 0ull;

    float4 q4[2], k4[2];
#pragma unroll
    for (int i = 0; i < 2; i++) {
        q4[i] = *(const float4*)(Q  + (size_t)(n0+lr[i])*QKVN + lc[i]);
        k4[i] = *(const float4*)(Kp + (size_t)(m0+lr[i])*QKVN + lc[i]);
    }
#pragma unroll
    for (int i = 0; i < 2; i++) {
        Qs[0][lc[i]+0][lr[i]] = q4[i].x; Qs[0][lc[i]+1][lr[i]] = q4[i].y;
        Qs[0][lc[i]+2][lr[i]] = q4[i].z; Qs[0][lc[i]+3][lr[i]] = q4[i].w;
        Ks[0][lc[i]+0][lr[i]] = k4[i].x; Ks[0][lc[i]+1][lr[i]] = k4[i].y;
        Ks[0][lc[i]+2][lr[i]] = k4[i].z; Ks[0][lc[i]+3][lr[i]] = k4[i].w;
    }
    __syncthreads();

    int buf = 0;
    for (int d0 = 16; d0 < HD; d0 += 16) {
#pragma unroll
        for (int i = 0; i < 2; i++) {
            q4[i] = *(const float4*)(Q  + (size_t)(n0+lr[i])*QKVN + d0 + lc[i]);
            k4[i] = *(const float4*)(Kp + (size_t)(m0+lr[i])*QKVN + d0 + lc[i]);
        }
#pragma unroll
        for (int k = 0; k < 16; k++) {
            float4 av0 = *(const float4*)&Qs[buf][k][ty*8];
            float4 av1 = *(const float4*)&Qs[buf][k][ty*8 + 4];
            unsigned long long b2[4];
            b2[0] = *(const unsigned long long*)&Ks[buf][k][tx*4];
            b2[1] = *(const unsigned long long*)&Ks[buf][k][tx*4 + 2];
            b2[2] = *(const unsigned long long*)&Ks[buf][k][64 + tx*4];
            b2[3] = *(const unsigned long long*)&Ks[buf][k][64 + tx*4 + 2];
            float a_[8] = {av0.x, av0.y, av0.z, av0.w, av1.x, av1.y, av1.z, av1.w};
#pragma unroll
            for (int i = 0; i < 8; i++) {
                unsigned long long a2 = pk2(a_[i]);
#pragma unroll
                for (int j = 0; j < 4; j++) fma2(accp[i][j], a2, b2[j]);
            }
        }
#pragma unroll
        for (int i = 0; i < 2; i++) {
            Qs[buf^1][lc[i]+0][lr[i]] = q4[i].x; Qs[buf^1][lc[i]+1][lr[i]] = q4[i].y;
            Qs[buf^1][lc[i]+2][lr[i]] = q4[i].z; Qs[buf^1][lc[i]+3][lr[i]] = q4[i].w;
            Ks[buf^1][lc[i]+0][lr[i]] = k4[i].x; Ks[buf^1][lc[i]+1][lr[i]] = k4[i].y;
            Ks[buf^1][lc[i]+2][lr[i]] = k4[i].z; Ks[buf^1][lc[i]+3][lr[i]] = k4[i].w;
        }
        __syncthreads();
        buf ^= 1;
    }
#pragma unroll
    for (int k = 0; k < 16; k++) {
        float4 av0 = *(const float4*)&Qs[buf][k][ty*8];
        float4 av1 = *(const float4*)&Qs[buf][k][ty*8 + 4];
        unsigned long long b2[4];
        b2[0] = *(const unsigned long long*)&Ks[buf][k][tx*4];
        b2[1] = *(const unsigned long long*)&Ks[buf][k][tx*4 + 2];
        b2[2] = *(const unsigned long long*)&Ks[buf][k][64 + tx*4];
        b2[3] = *(const unsigned long long*)&Ks[buf][k][64 + tx*4 + 2];
        float a_[8] = {av0.x, av0.y, av0.z, av0.w, av1.x, av1.y, av1.z, av1.w};
#pragma unroll
        for (int i = 0; i < 8; i++) {
            unsigned long long a2 = pk2(a_[i]);
#pragma unroll
            for (int j = 0; j < 4; j++) fma2(accp[i][j], a2, b2[j]);
        }
    }

#pragma unroll
    for (int i = 0; i < 8; i++) {
        size_t r = n0 + ty*8 + i;
        float4 v0 = acc2f4(accp[i][0], accp[i][1]);
        float4 v1 = acc2f4(accp[i][2], accp[i][3]);
        v0.x *= ATTSCALE; v0.y *= ATTSCALE; v0.z *= ATTSCALE; v0.w *= ATTSCALE;
        v1.x *= ATTSCALE; v1.y *= ATTSCALE; v1.z *= ATTSCALE; v1.w *= ATTSCALE;
        *(float4*)&Cp[r*SEQ + m0 + tx*4]      = v0;
        *(float4*)&Cp[r*SEQ + m0 + 64 + tx*4] = v1;
    }
}

// ---------------- softmax: one WARP per row of 1024 (shuffle-only, no barriers) ----------------
// 256 threads = 8 warps = 8 rows/block. Each lane holds 8 float4 = 32 values.
__global__ void __launch_bounds__(256) softmax_kernel(float* __restrict__ attn)
{
    int w = threadIdx.x >> 5, lane = threadIdx.x & 31;
    size_t row = (size_t)blockIdx.x * 8 + w;
    float4* p = (float4*)(attn + row * SEQ);
    float4 v[8];
    float mx = -3.0e38f;
#pragma unroll
    for (int i = 0; i < 8; i++) {
        v[i] = p[lane + 32*i];
        mx = fmaxf(mx, fmaxf(fmaxf(v[i].x, v[i].y), fmaxf(v[i].z, v[i].w)));
    }
#pragma unroll
    for (int o = 16; o > 0; o >>= 1) mx = fmaxf(mx, __shfl_xor_sync(0xffffffffu, mx, o));
    float s = 0.f;
#pragma unroll
    for (int i = 0; i < 8; i++) {
        v[i].x = __expf(v[i].x - mx); v[i].y = __expf(v[i].y - mx);
        v[i].z = __expf(v[i].z - mx); v[i].w = __expf(v[i].w - mx);
        s += (v[i].x + v[i].y) + (v[i].z + v[i].w);
    }
#pragma unroll
    for (int o = 16; o > 0; o >>= 1) s += __shfl_xor_sync(0xffffffffu, s, o);
    float inv = 1.f / s;
#pragma unroll
    for (int i = 0; i < 8; i++) {
        v[i].x *= inv; v[i].y *= inv; v[i].z *= inv; v[i].w *= inv;
        p[lane + 32*i] = v[i];
    }
}

// ---------------- attn @ V (double-buffered, f32x2, vector stores) ----------------
__global__ void __launch_bounds__(256) attn_av_kernel(
    const float* __restrict__ attn, const float* __restrict__ qkv,
    float* __restrict__ AO)
{
    int bh = blockIdx.y;
    int bb = bh / HEADS, h = bh % HEADS;
    const float* Ap = attn + (size_t)bh*SEQ*SEQ;
    const float* V  = qkv + (size_t)bb*SEQ*QKVN + 2*DIMC + h*HD;
    int n0 = blockIdx.x * 128;

    __shared__ __align__(16) float As[2][32][132];
    __shared__ __align__(16) float Vs[2][32][72];
    int tid = threadIdx.x;
    int tx = tid & 15, ty = tid >> 4;

    int arr[4], colc[4], vr[2], vc[2];
#pragma unroll
    for (int i = 0; i < 4; i++) {
        int f = tid + i*256;
        arr[i] = f >> 3; colc[i] = (f & 7) << 2;
    }
#pragma unroll
    for (int i = 0; i < 2; i++) {
        int f = tid + i*256;
        vr[i] = f >> 4; vc[i] = (f & 15) << 2;
    }

    unsigned long long accp[8][2];
#pragma unroll
    for (int i = 0; i < 8; i++)
#pragma unroll
        for (int j = 0; j < 2; j++) accp[i][j] = 0ull;

    float4 a4[4], v4[2];
#pragma unroll
    for (int i = 0; i < 4; i++)
        a4[i] = *(const float4*)(Ap + (size_t)(n0+arr[i])*SEQ + colc[i]);
#pragma unroll
    for (int i = 0; i < 2; i++)
        v4[i] = *(const float4*)(V + (size_t)vr[i]*QKVN + vc[i]);
#pragma unroll
    for (int i = 0; i < 4; i++) {
        As[0][colc[i]+0][arr[i]] = a4[i].x; As[0][colc[i]+1][arr[i]] = a4[i].y;
        As[0][colc[i]+2][arr[i]] = a4[i].z; As[0][colc[i]+3][arr[i]] = a4[i].w;
    }
#pragma unroll
    for (int i = 0; i < 2; i++)
        *(float4*)&Vs[0][vr[i]][vc[i]] = v4[i];
    __syncthreads();

    int buf = 0;
    for (int m0 = 32; m0 < SEQ; m0 += 32) {
#pragma unroll
        for (int i = 0; i < 4; i++)
            a4[i] = *(const float4*)(Ap + (size_t)(n0+arr[i])*SEQ + m0 + colc[i]);
#pragma unroll
        for (int i = 0; i < 2; i++)
            v4[i] = *(const float4*)(V + (size_t)(m0+vr[i])*QKVN + vc[i]);
#pragma unroll
        for (int k = 0; k < 32; k++) {
            float4 av0 = *(const float4*)&As[buf][k][ty*8];
            float4 av1 = *(const float4*)&As[buf][k][ty*8 + 4];
            unsigned long long b2[2];
            b2[0] = *(const unsigned long long*)&Vs[buf][k][tx*4];
            b2[1] = *(const unsigned long long*)&Vs[buf][k][tx*4 + 2];
            float a_[8] = {av0.x, av0.y, av0.z, av0.w, av1.x, av1.y, av1.z, av1.w};
#pragma unroll
            for (int i = 0; i < 8; i++) {
                unsigned long long a2 = pk2(a_[i]);
#pragma unroll
                for (int j = 0; j < 2; j++) fma2(accp[i][j], a2, b2[j]);
            }
        }
#pragma unroll
        for (int i = 0; i < 4; i++) {
            As[buf^1][colc[i]+0][arr[i]] = a4[i].x; As[buf^1][colc[i]+1][arr[i]] = a4[i].y;
            As[buf^1][colc[i]+2][arr[i]] = a4[i].z; As[buf^1][colc[i]+3][arr[i]] = a4[i].w;
        }
#pragma unroll
        for (int i = 0; i < 2; i++)
            *(float4*)&Vs[buf^1][vr[i]][vc[i]] = v4[i];
        __syncthreads();
        buf ^= 1;
    }
#pragma unroll
    for (int k = 0; k < 32; k++) {
        float4 av0 = *(const float4*)&As[buf][k][ty*8];
        float4 av1 = *(const float4*)&As[buf][k][ty*8 + 4];
        unsigned long long b2[2];
        b2[0] = *(const unsigned long long*)&Vs[buf][k][tx*4];
        b2[1] = *(const unsigned long long*)&Vs[buf][k][tx*4 + 2];
        float a_[8] = {av0.x, av0.y, av0.z, av0.w, av1.x, av1.y, av1.z, av1.w};
#pragma unroll
        for (int i = 0; i < 8; i++) {
            unsigned long long a2 = pk2(a_[i]);
#pragma unroll
            for (int j = 0; j < 2; j++) fma2(accp[i][j], a2, b2[j]);
        }
    }

#pragma unroll
    for (int i = 0; i < 8; i++) {
        size_t n = (size_t)bb*SEQ + n0 + ty*8 + i;
        float4 v0 = acc2f4(accp[i][0], accp[i][1]);
        *(float4*)&AO[n*DIMC + h*HD + tx*4] = v0;
    }
}

// ---------------- driver ----------------
extern "C" void kernel_launch(void* const* d_in, const int* in_sizes, int n_in,
                              void* d_out, int out_size)
{
    const float* x = (const float*)d_in[0];
    const float* P[25];
    for (int i = 0; i < 25; i++) P[i] = (const float*)d_in[i];

    float* out   = (float*)d_out;
    float* attn0 = out + (size_t)MTOK * DIMC;
    float* attn1 = attn0 + (size_t)BATCH*HEADS*SEQ*SEQ;

    float *H, *QKV, *AO, *X1, *X2, *HID;
    cudaGetSymbolAddress((void**)&H,   g_H);
    cudaGetSymbolAddress((void**)&QKV, g_QKV);
    cudaGetSymbolAddress((void**)&AO,  g_AO);
    cudaGetSymbolAddress((void**)&X1,  g_X1);
    cudaGetSymbolAddress((void**)&X2,  g_X2);
    cudaGetSymbolAddress((void**)&HID, g_HID);

    dim3 gQKV(QKVN/128, MTOK/128);     // (18, 32)  BM=128
    dim3 gPROJ(DIMC/128, MTOK/64);     // (6, 64)   BM=64 — better wave balance
    dim3 gMLP1(MLPH/128, MTOK/128);    // (24, 32)  BM=128
    dim3 gSC(SEQ/128, SEQ/128, BATCH*HEADS);  // (8, 8, 48)
    dim3 gAV(SEQ/128, BATCH*HEADS);           // (8, 48)
    int  gSM = BATCH*HEADS*SEQ/8;             // 6144 softmax blocks (8 rows each)
    int  gLN = MTOK/8;                        // 512 LN blocks (8 rows each)

    // ===== level 0: attention =====
    ln_kernel<<<gLN, 256>>>(x, P[5], P[6], H);
    sgemm_kernel<0,128><<<gQKV, 256>>>(H, P[1], P[2], nullptr, nullptr, QKV, MTOK, QKVN, DIMC);
    attn_scores_kernel<<<gSC, 256>>>(QKV, attn0);
    softmax_kernel<<<gSM, 256>>>(attn0);
    attn_av_kernel<<<gAV, 256>>>(attn0, QKV, AO);
    sgemm_kernel<2,64><<<gPROJ, 256>>>(AO, P[3], P[4], x, nullptr, X1, MTOK, DIMC, DIMC);

    // ===== level 1 (inner block on X1) =====
    ln_kernel<<<gLN, 256>>>(X1, P[17], P[18], H);
    sgemm_kernel<0,128><<<gQKV, 256>>>(H, P[13], P[14], nullptr, nullptr, QKV, MTOK, QKVN, DIMC);
    attn_scores_kernel<<<gSC, 256>>>(QKV, attn1);
    softmax_kernel<<<gSM, 256>>>(attn1);
    attn_av_kernel<<<gAV, 256>>>(attn1, QKV, AO);
    sgemm_kernel<2,64><<<gPROJ, 256>>>(AO, P[15], P[16], X1, nullptr, X2, MTOK, DIMC, DIMC);
    // inner MLP (MLP2 epilogue fuses the level-0 blend: X1 = 0.5*X1 + 0.5*(X2 + mlp_out))
    ln_kernel<<<gLN, 256>>>(X2, P[19], P[20], H);
    sgemm_kernel<1,128><<<gMLP1, 256>>>(H, P[21], P[22], nullptr, nullptr, HID, MTOK, MLPH, DIMC);
    sgemm_kernel<3,64><<<gPROJ, 256>>>(HID, P[23], P[24], X2, X1, X1, MTOK, DIMC, MLPH);

    // ===== level 0: MLP =====
    ln_kernel<<<gLN, 256>>>(X1, P[7], P[8], H);
    sgemm_kernel<1,128><<<gMLP1, 256>>>(H, P[9], P[10], nullptr, nullptr, HID, MTOK, MLPH, DIMC);
    sgemm_kernel<2,64><<<gPROJ, 256>>>(HID, P[11], P[12], X1, nullptr, out, MTOK, DIMC, MLPH);
}